// round 13
// baseline (speedup 1.0000x reference)
#include <cuda_runtime.h>
#include <cstdint>

#define THREADS 256
#define ROWS 32

// swizzled smem: byte offset of (row, 16B-chunk) within a tile
#define SW(row, chunk) ((((uint32_t)(row))<<9) | (((((uint32_t)(chunk)) ^ ((((uint32_t)(row))&7u)<<2)) & 31u)<<4))

// smem bytes: X(32r,16K) B0(32r,16K) B1(32r,16K) W(128r,64K)
#define OFF_X  0
#define OFF_B0 16384
#define OFF_B1 32768
#define OFF_W  49152
#define SMEM_BYTES 114688

__device__ float wbuf[8][16384];   // Wf,Uf,Wu,Uu,Wi,Ui,Wo,Uo : [n][k], tf32-rounded

__device__ __forceinline__ float tf32r(float v){
    uint32_t u; asm("cvt.rna.tf32.f32 %0, %1;" : "=r"(u) : "f"(v));
    return __uint_as_float(u);
}
__device__ __forceinline__ float sigf(float v){
    float t = __expf(-v);
    return __fdividef(1.0f, 1.0f + t);
}
__device__ __forceinline__ float tanhfast(float v){
    v = fminf(fmaxf(v, -15.0f), 15.0f);
    float t = __expf(-2.0f*v);
    return __fdividef(1.0f - t, 1.0f + t);
}
__device__ __forceinline__ void cpa16(uint32_t s, const float* g){
    asm volatile("cp.async.cg.shared.global [%0], [%1], 16;\n" :: "r"(s), "l"(g));
}
#define CP_COMMIT() asm volatile("cp.async.commit_group;\n" ::: "memory")
#define CP_WAIT(n)  asm volatile("cp.async.wait_group %0;\n" :: "n"(n) : "memory")

// 32-row x 128-col tile (swizzled), 256 threads
__device__ __forceinline__ void cpa_t32(uint32_t sdst, const float* __restrict__ src,
                                        int rs, int tid){
    #pragma unroll
    for (int i=0;i<4;i++){
        int e = tid + i*THREADS;
        int row = e >> 5, c = e & 31;
        cpa16(sdst + SW(row, c), src + (size_t)row*rs + c*4);
    }
}
// 128-row weight tile from wbuf (gmem rows contiguous 512B)
__device__ __forceinline__ void cpa_w(uint32_t sdst, const float* __restrict__ src, int tid){
    #pragma unroll
    for (int i=0;i<16;i++){
        int e = tid + i*THREADS;
        int row = e >> 5, c = e & 31;
        cpa16(sdst + SW(row, c), src + row*128 + c*4);
    }
}

__device__ __forceinline__ void mma8(float* c, const uint32_t* a, const uint32_t* b){
    asm volatile(
      "mma.sync.aligned.m16n8k8.row.col.f32.tf32.tf32.f32 "
      "{%0,%1,%2,%3},{%4,%5,%6,%7},{%8,%9},{%0,%1,%2,%3};\n"
      : "+f"(c[0]), "+f"(c[1]), "+f"(c[2]), "+f"(c[3])
      : "r"(a[0]), "r"(a[1]), "r"(a[2]), "r"(a[3]),
        "r"(b[0]), "r"(b[1]));
}
__device__ __forceinline__ void ldsm4(uint32_t* d, uint32_t saddr){
    asm volatile("ldmatrix.sync.aligned.m8n8.x4.shared.b16 {%0,%1,%2,%3}, [%4];\n"
      : "=r"(d[0]),"=r"(d[1]),"=r"(d[2]),"=r"(d[3]) : "r"(saddr));
}

// 32x128x128 tf32 GEMM; 8 warps as 2(m) x 4(n); warp tile 16 x 32. Swizzled operands.
__device__ __forceinline__ void gemm32(float (&acc)[4][4], uint32_t Ab, uint32_t Bb,
                                       int lane, int wm, int wn)
{
    uint32_t arow = wm*16 + (lane&7) + ((lane>>3)&1)*8;
    uint32_t acx  = (lane>>4)&1;
    uint32_t axor = (arow&7)<<2;
    uint32_t abase = Ab + (arow<<9);
    uint32_t brow = wn*32 + (lane&7) + ((lane>>4)&1)*8;
    uint32_t bcx  = (lane>>3)&1;
    uint32_t bxor = (brow&7)<<2;
    uint32_t bb0 = Bb + (brow<<9);
    uint32_t bb1 = bb0 + (16u<<9);

    #pragma unroll
    for (int k8=0;k8<16;k8++){
        uint32_t a[4], b0[4], b1[4];
        uint32_t ac = (((uint32_t)(k8*2) + acx) ^ axor) << 4;
        uint32_t bc = (((uint32_t)(k8*2) + bcx) ^ bxor) << 4;
        ldsm4(a,  abase + ac);
        ldsm4(b0, bb0 + bc);
        ldsm4(b1, bb1 + bc);
        mma8(acc[0], a, &b0[0]);
        mma8(acc[1], a, &b0[2]);
        mma8(acc[2], a, &b1[0]);
        mma8(acc[3], a, &b1[2]);
    }
}

#define ZERO_ACC(A) { _Pragma("unroll") for(int _n=0;_n<4;_n++) _Pragma("unroll") for(int _e=0;_e<4;_e++) (A)[_n][_e]=0.0f; }

// ---- prep: transpose + tf32-round all 8 weight matrices ----------------
__global__ void prep_weights(const float* __restrict__ Wf, const float* __restrict__ Uf,
                             const float* __restrict__ Wu, const float* __restrict__ Uu,
                             const float* __restrict__ Wi, const float* __restrict__ Ui,
                             const float* __restrict__ Wo, const float* __restrict__ Uo)
{
    const float* srcs[8] = {Wf,Uf,Wu,Uu,Wi,Ui,Wo,Uo};
    const float* s = srcs[blockIdx.x];
    float* d = wbuf[blockIdx.x];
    for (int i = threadIdx.x; i < 128*128; i += blockDim.x){
        int n = i >> 7, k = i & 127;
        d[n*128 + k] = tf32r(s[k*128 + n]);
    }
}

__global__ void __launch_bounds__(THREADS, 2)
treelstm_kernel(const float* __restrict__ x,
                const float* __restrict__ child_h,
                const float* __restrict__ child_c,
                const float* __restrict__ bi, const float* __restrict__ bo,
                const float* __restrict__ bu, const float* __restrict__ bf,
                float* __restrict__ out, int N)
{
    extern __shared__ char smem[];
    uint32_t sb;
    asm("{ .reg .u64 t; cvta.to.shared.u64 t, %1; cvt.u32.u64 %0, t; }" : "=r"(sb) : "l"(smem));
    const uint32_t Xb  = sb + OFF_X;
    const uint32_t B0b = sb + OFF_B0;
    const uint32_t B1b = sb + OFF_B1;
    const uint32_t Wb  = sb + OFF_W;

    const int tid  = threadIdx.x;
    const int lane = tid & 31;
    const int g    = lane >> 2;
    const int r    = lane & 3;
    const int wid  = tid >> 5;
    const int wm   = wid & 1;           // 16-row half
    const int wn   = wid >> 1;          // 32-col group
    const int m0   = blockIdx.x * ROWS;

    const int Rr   = wm*16 + g;         // owned rows: Rr, Rr+8 (tile-local)
    const int Rg   = m0 + Rr;           // global rows: Rg, Rg+8
    // epilogue smem float2 address pieces: col C0 = wn*32 + nt*8 + 2*r
    // chunk(C0) = C0>>2, inner = (C0&3)*4

    float acc [4][4];
    float cacc[4][4];
    float xfv [4][4];   // xf during children, u during gates
    float hs  [4][4];

    #pragma unroll
    for (int nt=0;nt<4;nt++)
      #pragma unroll
      for (int e=0;e<4;e++){ cacc[nt][e]=0.f; hs[nt][e]=0.f; }

    // ---- prologue: x + Wf | ch0 ----------------------------------------
    cpa_t32(Xb, x + (size_t)m0*128, 128, tid);
    cpa_w  (Wb, wbuf[0], tid);
    CP_COMMIT();                                     // GA: x + Wf
    cpa_t32(B0b, child_h + ((size_t)m0*8 + 0)*128, 8*128, tid);
    CP_COMMIT();                                     // GB: ch0

    CP_WAIT(1); __syncthreads();                     // x + Wf visible
    // round x in place (own chunks)
    #pragma unroll
    for (int i=0;i<4;i++){
        int e = tid + i*THREADS;
        int row = e>>5, c = e&31;
        float4* p = reinterpret_cast<float4*>(smem + OFF_X + SW(row,c));
        float4 v = *p;
        v.x=tf32r(v.x); v.y=tf32r(v.y); v.z=tf32r(v.z); v.w=tf32r(v.w);
        *p = v;
    }
    __syncthreads();

    // ---- phase 1: xf = x @ Wf + bf --------------------------------------
    ZERO_ACC(acc);
    gemm32(acc, Xb, Wb, lane, wm, wn);
    __syncthreads();                                 // W free
    cpa_w(Wb, wbuf[1], tid); CP_COMMIT();            // GC: Uf
    cpa_t32(B1b, child_h + ((size_t)m0*8 + 1)*128, 8*128, tid);
    CP_COMMIT();                                     // GD: ch1

    #pragma unroll
    for (int nt=0;nt<4;nt++){
        int C0 = wn*32 + nt*8 + 2*r;
        float2 bv = *reinterpret_cast<const float2*>(bf + C0);
        xfv[nt][0] = acc[nt][0] + bv.x;
        xfv[nt][1] = acc[nt][1] + bv.y;
        xfv[nt][2] = acc[nt][2] + bv.x;
        xfv[nt][3] = acc[nt][3] + bv.y;
    }

    // ---- phase 2: children (B0/B1 ping-pong, Uf resident in W) ----------
    for (int k=0;k<8;k++){
        uint32_t buf = (k&1) ? B1b : B0b;
        char*   bufp = smem + ((k&1) ? OFF_B1 : OFF_B0);
        if (k<7) { CP_WAIT(1); } else { CP_WAIT(0); }    // ch_k (+Uf at k=0) done
        __syncthreads();

        // hs += own slice of raw child tile (swizzled float2 reads)
        #pragma unroll
        for (int nt=0;nt<4;nt++){
            int C0 = wn*32 + nt*8 + 2*r;
            int ck = C0>>2, inb = (C0&3)<<2;
            float2 v0 = *reinterpret_cast<const float2*>(bufp + SW(Rr,   ck) + inb);
            float2 v1 = *reinterpret_cast<const float2*>(bufp + SW(Rr+8, ck) + inb);
            hs[nt][0] += v0.x; hs[nt][1] += v0.y;
            hs[nt][2] += v1.x; hs[nt][3] += v1.y;
        }
        // prefetch child_c[k]
        float2 cc0[4], cc1[4];
        #pragma unroll
        for (int nt=0;nt<4;nt++){
            int C0 = wn*32 + nt*8 + 2*r;
            cc0[nt] = __ldg(reinterpret_cast<const float2*>(child_c + ((size_t)Rg    *8 + k)*128 + C0));
            cc1[nt] = __ldg(reinterpret_cast<const float2*>(child_c + ((size_t)(Rg+8)*8 + k)*128 + C0));
        }

        ZERO_ACC(acc);
        gemm32(acc, buf, Wb, lane, wm, wn);            // ch_k @ Uf

        #pragma unroll
        for (int nt=0;nt<4;nt++){
            cacc[nt][0] += sigf(xfv[nt][0] + acc[nt][0]) * cc0[nt].x;
            cacc[nt][1] += sigf(xfv[nt][1] + acc[nt][1]) * cc0[nt].y;
            cacc[nt][2] += sigf(xfv[nt][2] + acc[nt][2]) * cc1[nt].x;
            cacc[nt][3] += sigf(xfv[nt][3] + acc[nt][3]) * cc1[nt].y;
        }

        __syncthreads();                               // buf free
        if (k+2 < 8){
            cpa_t32(buf, child_h + ((size_t)m0*8 + (k+2))*128, 8*128, tid);
            CP_COMMIT();
        }
    }

    // ---- gate prologue: hs -> B0 (tf32, swizzled) -----------------------
    {
        char* b0p = smem + OFF_B0;
        #pragma unroll
        for (int nt=0;nt<4;nt++){
            int C0 = wn*32 + nt*8 + 2*r;
            int ck = C0>>2, inb = (C0&3)<<2;
            *reinterpret_cast<float2*>(b0p + SW(Rr,   ck) + inb) =
                make_float2(tf32r(hs[nt][0]), tf32r(hs[nt][1]));
            *reinterpret_cast<float2*>(b0p + SW(Rr+8, ck) + inb) =
                make_float2(tf32r(hs[nt][2]), tf32r(hs[nt][3]));
        }
    }
    __syncthreads();                                   // W free (children done), hs visible
    cpa_w(Wb, wbuf[2], tid); CP_COMMIT();              // Wu

    const float* bs[3] = {bu, bi, bo};

    // ---- phase 3: gates u, i, o ------------------------------------------
    for (int gate=0; gate<3; gate++){
        CP_WAIT(0); __syncthreads();                   // W_gate visible
        ZERO_ACC(acc);
        gemm32(acc, Xb, Wb, lane, wm, wn);             // x @ W_g
        __syncthreads();                               // W free
        cpa_w(Wb, wbuf[3 + 2*gate], tid); CP_COMMIT(); // U_g
        CP_WAIT(0); __syncthreads();
        gemm32(acc, B0b, Wb, lane, wm, wn);            // + hs @ U_g
        __syncthreads();                               // W free
        if (gate<2){ cpa_w(Wb, wbuf[4 + 2*gate], tid); CP_COMMIT(); }  // next W_g

        const float* bp = bs[gate];
        #pragma unroll
        for (int nt=0;nt<4;nt++){
            int C0 = wn*32 + nt*8 + 2*r;
            float2 bv = *reinterpret_cast<const float2*>(bp + C0);
            float p0 = acc[nt][0] + bv.x;
            float p1 = acc[nt][1] + bv.y;
            float p2 = acc[nt][2] + bv.x;
            float p3 = acc[nt][3] + bv.y;
            if (gate == 0){
                xfv[nt][0] = tanhfast(p0);
                xfv[nt][1] = tanhfast(p1);
                xfv[nt][2] = tanhfast(p2);
                xfv[nt][3] = tanhfast(p3);
            } else if (gate == 1){
                cacc[nt][0] += sigf(p0) * xfv[nt][0];
                cacc[nt][1] += sigf(p1) * xfv[nt][1];
                cacc[nt][2] += sigf(p2) * xfv[nt][2];
                cacc[nt][3] += sigf(p3) * xfv[nt][3];
            } else {
                float c0 = cacc[nt][0], c1 = cacc[nt][1];
                float c2 = cacc[nt][2], c3 = cacc[nt][3];
                float h0 = sigf(p0) * tanhfast(c0);
                float h1 = sigf(p1) * tanhfast(c1);
                float h2 = sigf(p2) * tanhfast(c2);
                float h3 = sigf(p3) * tanhfast(c3);
                float* outh = out;
                float* outc = out + (size_t)N*128;
                *reinterpret_cast<float2*>(outh + (size_t) Rg   *128 + C0) = make_float2(h0,h1);
                *reinterpret_cast<float2*>(outh + (size_t)(Rg+8)*128 + C0) = make_float2(h2,h3);
                *reinterpret_cast<float2*>(outc + (size_t) Rg   *128 + C0) = make_float2(c0,c1);
                *reinterpret_cast<float2*>(outc + (size_t)(Rg+8)*128 + C0) = make_float2(c2,c3);
            }
        }
    }
}

extern "C" void kernel_launch(void* const* d_in, const int* in_sizes, int n_in,
                              void* d_out, int out_size)
{
    const float* x       = (const float*)d_in[0];
    const float* child_h = (const float*)d_in[1];
    const float* child_c = (const float*)d_in[2];
    const float* Wi = (const float*)d_in[3];
    const float* bi = (const float*)d_in[4];
    const float* Ui = (const float*)d_in[5];
    const float* Wo = (const float*)d_in[6];
    const float* bo = (const float*)d_in[7];
    const float* Uo = (const float*)d_in[8];
    const float* Wu = (const float*)d_in[9];
    const float* bu = (const float*)d_in[10];
    const float* Uu = (const float*)d_in[11];
    const float* Wf = (const float*)d_in[12];
    const float* bf = (const float*)d_in[13];
    const float* Uf = (const float*)d_in[14];
    float* out = (float*)d_out;

    int N = in_sizes[0] / 128;
    int blocks = N / ROWS;

    prep_weights<<<8, 256>>>(Wf, Uf, Wu, Uu, Wi, Ui, Wo, Uo);

    cudaFuncSetAttribute(treelstm_kernel,
                         cudaFuncAttributeMaxDynamicSharedMemorySize, SMEM_BYTES);
    treelstm_kernel<<<blocks, THREADS, SMEM_BYTES>>>(
        x, child_h, child_c, bi, bo, bu, bf, out, N);
}

// round 14
// speedup vs baseline: 2.4315x; 2.4315x over previous
#include <cuda_runtime.h>
#include <cstdint>

#define THREADS 256
#define ROWS 32

// swizzled smem: byte offset of (row, 16B-chunk) within a tile.
// chunk ^ (row&7) permutes bank groups (chunk mod 8) -> conflict-free ldmatrix.
#define SW(row, chunk) ((((uint32_t)(row))<<9) | (((((uint32_t)(chunk)) ^ (((uint32_t)(row))&7u)) & 31u)<<4))

// smem bytes: X(32r,16K) B0(32r,16K) B1(32r,16K) W(128r,64K)
#define OFF_X  0
#define OFF_B0 16384
#define OFF_B1 32768
#define OFF_W  49152
#define SMEM_BYTES 114688

__device__ float wbuf[8][16384];   // Wf,Uf,Wu,Uu,Wi,Ui,Wo,Uo : [n][k], tf32-rounded

__device__ __forceinline__ float tf32r(float v){
    uint32_t u; asm("cvt.rna.tf32.f32 %0, %1;" : "=r"(u) : "f"(v));
    return __uint_as_float(u);
}
__device__ __forceinline__ float sigf(float v){
    float t = __expf(-v);
    return __fdividef(1.0f, 1.0f + t);
}
__device__ __forceinline__ float tanhfast(float v){
    v = fminf(fmaxf(v, -15.0f), 15.0f);
    float t = __expf(-2.0f*v);
    return __fdividef(1.0f - t, 1.0f + t);
}
__device__ __forceinline__ void cpa16(uint32_t s, const float* g){
    asm volatile("cp.async.cg.shared.global [%0], [%1], 16;\n" :: "r"(s), "l"(g));
}
#define CP_COMMIT() asm volatile("cp.async.commit_group;\n" ::: "memory")
#define CP_WAIT(n)  asm volatile("cp.async.wait_group %0;\n" :: "n"(n) : "memory")

// 32-row x 128-col tile (swizzled), 256 threads
__device__ __forceinline__ void cpa_t32(uint32_t sdst, const float* __restrict__ src,
                                        int rs, int tid){
    #pragma unroll
    for (int i=0;i<4;i++){
        int e = tid + i*THREADS;
        int row = e >> 5, c = e & 31;
        cpa16(sdst + SW(row, c), src + (size_t)row*rs + c*4);
    }
}
// 128-row weight tile from wbuf (gmem rows contiguous 512B)
__device__ __forceinline__ void cpa_w(uint32_t sdst, const float* __restrict__ src, int tid){
    #pragma unroll
    for (int i=0;i<16;i++){
        int e = tid + i*THREADS;
        int row = e >> 5, c = e & 31;
        cpa16(sdst + SW(row, c), src + row*128 + c*4);
    }
}

__device__ __forceinline__ void mma8(float* c, const uint32_t* a, const uint32_t* b){
    asm volatile(
      "mma.sync.aligned.m16n8k8.row.col.f32.tf32.tf32.f32 "
      "{%0,%1,%2,%3},{%4,%5,%6,%7},{%8,%9},{%0,%1,%2,%3};\n"
      : "+f"(c[0]), "+f"(c[1]), "+f"(c[2]), "+f"(c[3])
      : "r"(a[0]), "r"(a[1]), "r"(a[2]), "r"(a[3]),
        "r"(b[0]), "r"(b[1]));
}
__device__ __forceinline__ void ldsm4(uint32_t* d, uint32_t saddr){
    asm volatile("ldmatrix.sync.aligned.m8n8.x4.shared.b16 {%0,%1,%2,%3}, [%4];\n"
      : "=r"(d[0]),"=r"(d[1]),"=r"(d[2]),"=r"(d[3]) : "r"(saddr));
}

// 32x128x128 tf32 GEMM; 8 warps as 2(m) x 4(n); warp tile 16 x 32. Swizzled operands.
__device__ __forceinline__ void gemm32(float (&acc)[4][4], uint32_t Ab, uint32_t Bb,
                                       int lane, int wm, int wn)
{
    uint32_t arow = wm*16 + (lane&7) + ((lane>>3)&1)*8;
    uint32_t acx  = (lane>>4)&1;
    uint32_t axor = arow & 7u;
    uint32_t abase = Ab + (arow<<9);
    uint32_t brow = wn*32 + (lane&7) + ((lane>>4)&1)*8;
    uint32_t bcx  = (lane>>3)&1;
    uint32_t bxor = brow & 7u;
    uint32_t bb0 = Bb + (brow<<9);
    uint32_t bb1 = bb0 + (16u<<9);

    #pragma unroll
    for (int k8=0;k8<16;k8++){
        uint32_t a[4], b0[4], b1[4];
        uint32_t ac = (((uint32_t)(k8*2) + acx) ^ axor) << 4;
        uint32_t bc = (((uint32_t)(k8*2) + bcx) ^ bxor) << 4;
        ldsm4(a,  abase + ac);
        ldsm4(b0, bb0 + bc);
        ldsm4(b1, bb1 + bc);
        mma8(acc[0], a, &b0[0]);
        mma8(acc[1], a, &b0[2]);
        mma8(acc[2], a, &b1[0]);
        mma8(acc[3], a, &b1[2]);
    }
}

#define ZERO_ACC(A) { _Pragma("unroll") for(int _n=0;_n<4;_n++) _Pragma("unroll") for(int _e=0;_e<4;_e++) (A)[_n][_e]=0.0f; }

// ---- prep: transpose + tf32-round all 8 weight matrices ----------------
__global__ void prep_weights(const float* __restrict__ Wf, const float* __restrict__ Uf,
                             const float* __restrict__ Wu, const float* __restrict__ Uu,
                             const float* __restrict__ Wi, const float* __restrict__ Ui,
                             const float* __restrict__ Wo, const float* __restrict__ Uo)
{
    const float* srcs[8] = {Wf,Uf,Wu,Uu,Wi,Ui,Wo,Uo};
    const float* s = srcs[blockIdx.x];
    float* d = wbuf[blockIdx.x];
    for (int i = threadIdx.x; i < 128*128; i += blockDim.x){
        int n = i >> 7, k = i & 127;
        d[n*128 + k] = tf32r(s[k*128 + n]);
    }
}

__global__ void __launch_bounds__(THREADS, 2)
treelstm_kernel(const float* __restrict__ x,
                const float* __restrict__ child_h,
                const float* __restrict__ child_c,
                const float* __restrict__ bi, const float* __restrict__ bo,
                const float* __restrict__ bu, const float* __restrict__ bf,
                float* __restrict__ out, int N)
{
    extern __shared__ char smem[];
    uint32_t sb;
    asm("{ .reg .u64 t; cvta.to.shared.u64 t, %1; cvt.u32.u64 %0, t; }" : "=r"(sb) : "l"(smem));
    const uint32_t Xb  = sb + OFF_X;
    const uint32_t B0b = sb + OFF_B0;
    const uint32_t B1b = sb + OFF_B1;
    const uint32_t Wb  = sb + OFF_W;

    const int tid  = threadIdx.x;
    const int lane = tid & 31;
    const int g    = lane >> 2;
    const int r    = lane & 3;
    const int wid  = tid >> 5;
    const int wm   = wid & 1;           // 16-row half
    const int wn   = wid >> 1;          // 32-col group
    const int m0   = blockIdx.x * ROWS;

    const int Rr   = wm*16 + g;         // owned rows: Rr, Rr+8 (tile-local)
    const int Rg   = m0 + Rr;           // global rows: Rg, Rg+8

    float acc [4][4];
    float cacc[4][4];
    float xfv [4][4];   // xf during children, u during gates
    float hs  [4][4];

    #pragma unroll
    for (int nt=0;nt<4;nt++)
      #pragma unroll
      for (int e=0;e<4;e++){ cacc[nt][e]=0.f; hs[nt][e]=0.f; }

    // ---- prologue: x + Wf | ch0 ----------------------------------------
    cpa_t32(Xb, x + (size_t)m0*128, 128, tid);
    cpa_w  (Wb, wbuf[0], tid);
    CP_COMMIT();                                     // GA: x + Wf
    cpa_t32(B0b, child_h + ((size_t)m0*8 + 0)*128, 8*128, tid);
    CP_COMMIT();                                     // GB: ch0

    CP_WAIT(1); __syncthreads();                     // x + Wf visible
    // round x in place (own chunks)
    #pragma unroll
    for (int i=0;i<4;i++){
        int e = tid + i*THREADS;
        int row = e>>5, c = e&31;
        float4* p = reinterpret_cast<float4*>(smem + OFF_X + SW(row,c));
        float4 v = *p;
        v.x=tf32r(v.x); v.y=tf32r(v.y); v.z=tf32r(v.z); v.w=tf32r(v.w);
        *p = v;
    }
    __syncthreads();

    // ---- phase 1: xf = x @ Wf + bf --------------------------------------
    ZERO_ACC(acc);
    gemm32(acc, Xb, Wb, lane, wm, wn);
    __syncthreads();                                 // W free
    cpa_w(Wb, wbuf[1], tid); CP_COMMIT();            // GC: Uf
    cpa_t32(B1b, child_h + ((size_t)m0*8 + 1)*128, 8*128, tid);
    CP_COMMIT();                                     // GD: ch1

    #pragma unroll
    for (int nt=0;nt<4;nt++){
        int C0 = wn*32 + nt*8 + 2*r;
        float2 bv = *reinterpret_cast<const float2*>(bf + C0);
        xfv[nt][0] = acc[nt][0] + bv.x;
        xfv[nt][1] = acc[nt][1] + bv.y;
        xfv[nt][2] = acc[nt][2] + bv.x;
        xfv[nt][3] = acc[nt][3] + bv.y;
    }

    // ---- phase 2: children (B0/B1 ping-pong, Uf resident in W) ----------
    for (int k=0;k<8;k++){
        uint32_t buf = (k&1) ? B1b : B0b;
        char*   bufp = smem + ((k&1) ? OFF_B1 : OFF_B0);
        if (k<7) { CP_WAIT(1); } else { CP_WAIT(0); }    // ch_k (+Uf at k=0) done
        __syncthreads();

        // hs += own slice of raw child tile (swizzled float2 reads)
        #pragma unroll
        for (int nt=0;nt<4;nt++){
            int C0 = wn*32 + nt*8 + 2*r;
            int ck = C0>>2, inb = (C0&3)<<2;
            float2 v0 = *reinterpret_cast<const float2*>(bufp + SW(Rr,   ck) + inb);
            float2 v1 = *reinterpret_cast<const float2*>(bufp + SW(Rr+8, ck) + inb);
            hs[nt][0] += v0.x; hs[nt][1] += v0.y;
            hs[nt][2] += v1.x; hs[nt][3] += v1.y;
        }
        // prefetch child_c[k]
        float2 cc0[4], cc1[4];
        #pragma unroll
        for (int nt=0;nt<4;nt++){
            int C0 = wn*32 + nt*8 + 2*r;
            cc0[nt] = __ldg(reinterpret_cast<const float2*>(child_c + ((size_t)Rg    *8 + k)*128 + C0));
            cc1[nt] = __ldg(reinterpret_cast<const float2*>(child_c + ((size_t)(Rg+8)*8 + k)*128 + C0));
        }

        ZERO_ACC(acc);
        gemm32(acc, buf, Wb, lane, wm, wn);            // ch_k @ Uf

        #pragma unroll
        for (int nt=0;nt<4;nt++){
            cacc[nt][0] += sigf(xfv[nt][0] + acc[nt][0]) * cc0[nt].x;
            cacc[nt][1] += sigf(xfv[nt][1] + acc[nt][1]) * cc0[nt].y;
            cacc[nt][2] += sigf(xfv[nt][2] + acc[nt][2]) * cc1[nt].x;
            cacc[nt][3] += sigf(xfv[nt][3] + acc[nt][3]) * cc1[nt].y;
        }

        __syncthreads();                               // buf free
        if (k+2 < 8){
            cpa_t32(buf, child_h + ((size_t)m0*8 + (k+2))*128, 8*128, tid);
            CP_COMMIT();
        }
    }

    // ---- gate prologue: hs -> B0 (tf32, swizzled) -----------------------
    {
        char* b0p = smem + OFF_B0;
        #pragma unroll
        for (int nt=0;nt<4;nt++){
            int C0 = wn*32 + nt*8 + 2*r;
            int ck = C0>>2, inb = (C0&3)<<2;
            *reinterpret_cast<float2*>(b0p + SW(Rr,   ck) + inb) =
                make_float2(tf32r(hs[nt][0]), tf32r(hs[nt][1]));
            *reinterpret_cast<float2*>(b0p + SW(Rr+8, ck) + inb) =
                make_float2(tf32r(hs[nt][2]), tf32r(hs[nt][3]));
        }
    }
    __syncthreads();                                   // W free (children done), hs visible
    cpa_w(Wb, wbuf[2], tid); CP_COMMIT();              // Wu

    const float* bs[3] = {bu, bi, bo};

    // ---- phase 3: gates u, i, o ------------------------------------------
    for (int gate=0; gate<3; gate++){
        CP_WAIT(0); __syncthreads();                   // W_gate visible
        ZERO_ACC(acc);
        gemm32(acc, Xb, Wb, lane, wm, wn);             // x @ W_g
        __syncthreads();                               // W free
        cpa_w(Wb, wbuf[3 + 2*gate], tid); CP_COMMIT(); // U_g
        CP_WAIT(0); __syncthreads();
        gemm32(acc, B0b, Wb, lane, wm, wn);            // + hs @ U_g
        __syncthreads();                               // W free
        if (gate<2){ cpa_w(Wb, wbuf[4 + 2*gate], tid); CP_COMMIT(); }  // next W_g

        const float* bp = bs[gate];
        #pragma unroll
        for (int nt=0;nt<4;nt++){
            int C0 = wn*32 + nt*8 + 2*r;
            float2 bv = *reinterpret_cast<const float2*>(bp + C0);
            float p0 = acc[nt][0] + bv.x;
            float p1 = acc[nt][1] + bv.y;
            float p2 = acc[nt][2] + bv.x;
            float p3 = acc[nt][3] + bv.y;
            if (gate == 0){
                xfv[nt][0] = tanhfast(p0);
                xfv[nt][1] = tanhfast(p1);
                xfv[nt][2] = tanhfast(p2);
                xfv[nt][3] = tanhfast(p3);
            } else if (gate == 1){
                cacc[nt][0] += sigf(p0) * xfv[nt][0];
                cacc[nt][1] += sigf(p1) * xfv[nt][1];
                cacc[nt][2] += sigf(p2) * xfv[nt][2];
                cacc[nt][3] += sigf(p3) * xfv[nt][3];
            } else {
                float c0 = cacc[nt][0], c1 = cacc[nt][1];
                float c2 = cacc[nt][2], c3 = cacc[nt][3];
                float h0 = sigf(p0) * tanhfast(c0);
                float h1 = sigf(p1) * tanhfast(c1);
                float h2 = sigf(p2) * tanhfast(c2);
                float h3 = sigf(p3) * tanhfast(c3);
                float* outh = out;
                float* outc = out + (size_t)N*128;
                *reinterpret_cast<float2*>(outh + (size_t) Rg   *128 + C0) = make_float2(h0,h1);
                *reinterpret_cast<float2*>(outh + (size_t)(Rg+8)*128 + C0) = make_float2(h2,h3);
                *reinterpret_cast<float2*>(outc + (size_t) Rg   *128 + C0) = make_float2(c0,c1);
                *reinterpret_cast<float2*>(outc + (size_t)(Rg+8)*128 + C0) = make_float2(c2,c3);
            }
        }
    }
}

extern "C" void kernel_launch(void* const* d_in, const int* in_sizes, int n_in,
                              void* d_out, int out_size)
{
    const float* x       = (const float*)d_in[0];
    const float* child_h = (const float*)d_in[1];
    const float* child_c = (const float*)d_in[2];
    const float* Wi = (const float*)d_in[3];
    const float* bi = (const float*)d_in[4];
    const float* Ui = (const float*)d_in[5];
    const float* Wo = (const float*)d_in[6];
    const float* bo = (const float*)d_in[7];
    const float* Uo = (const float*)d_in[8];
    const float* Wu = (const float*)d_in[9];
    const float* bu = (const float*)d_in[10];
    const float* Uu = (const float*)d_in[11];
    const float* Wf = (const float*)d_in[12];
    const float* bf = (const float*)d_in[13];
    const float* Uf = (const float*)d_in[14];
    float* out = (float*)d_out;

    int N = in_sizes[0] / 128;
    int blocks = N / ROWS;

    prep_weights<<<8, 256>>>(Wf, Uf, Wu, Uu, Wi, Ui, Wo, Uo);

    cudaFuncSetAttribute(treelstm_kernel,
                         cudaFuncAttributeMaxDynamicSharedMemorySize, SMEM_BYTES);
    treelstm_kernel<<<blocks, THREADS, SMEM_BYTES>>>(
        x, child_h, child_c, bi, bo, bu, bf, out, N);
}

// round 15
// speedup vs baseline: 3.4148x; 1.4044x over previous
#include <cuda_runtime.h>
#include <cuda_fp16.h>
#include <cstdint>

#define THREADS 256
#define ROWS 32

// f32 staging tile: 32 rows x 128 f32, 512B/row, 32x16B chunks, bank-group swizzle
#define SWF(row, chunk) ((((uint32_t)(row))<<9) | (((((uint32_t)(chunk)) ^ (((uint32_t)(row))&7u)) & 31u)<<4))
// fp16 tile: rows x 128 halves, 256B/row, 16x16B chunks
#define SWH(row, chunk) ((((uint32_t)(row))<<8) | (((((uint32_t)(chunk)) ^ (((uint32_t)(row))&7u)) & 15u)<<4))

// smem: XH(8K) HSH(8K) BH(8K) B0(16K) B1(16K) W(32K) = 88KB -> 2 CTAs/SM
#define OFF_XH  0
#define OFF_HSH 8192
#define OFF_BH  16384
#define OFF_B0  24576
#define OFF_B1  40960
#define OFF_W   57344
#define SMEM_BYTES 90112

__device__ __half wimg[8][16384];   // Wf,Uf,Wu,Uu,Wi,Ui,Wo,Uo : [n][k] fp16, pre-swizzled image

__device__ __forceinline__ float sigf(float v){
    float t = __expf(-v);
    return __fdividef(1.0f, 1.0f + t);
}
__device__ __forceinline__ float tanhfast(float v){
    v = fminf(fmaxf(v, -15.0f), 15.0f);
    float t = __expf(-2.0f*v);
    return __fdividef(1.0f - t, 1.0f + t);
}
__device__ __forceinline__ void cpa16(uint32_t s, const void* g){
    asm volatile("cp.async.cg.shared.global [%0], [%1], 16;\n" :: "r"(s), "l"(g));
}
#define CP_COMMIT() asm volatile("cp.async.commit_group;\n" ::: "memory")
#define CP_WAIT(n)  asm volatile("cp.async.wait_group %0;\n" :: "n"(n) : "memory")

// 32-row x 128-col f32 tile -> swizzled staging
__device__ __forceinline__ void cpa_t32(uint32_t sdst, const float* __restrict__ src,
                                        int rs, int tid){
    #pragma unroll
    for (int i=0;i<4;i++){
        int e = tid + i*THREADS;
        int row = e >> 5, c = e & 31;
        cpa16(sdst + SWF(row, c), src + (size_t)row*rs + c*4);
    }
}
// 32KB fp16 weight image (pre-swizzled) -> linear copy
__device__ __forceinline__ void cpa_w(uint32_t sdst, const __half* __restrict__ src, int tid){
    const char* s = (const char*)src;
    #pragma unroll
    for (int i=0;i<8;i++){
        int idx = tid + i*THREADS;
        cpa16(sdst + (uint32_t)idx*16u, s + (size_t)idx*16);
    }
}

__device__ __forceinline__ void ldsm4(uint32_t* d, uint32_t saddr){
    asm volatile("ldmatrix.sync.aligned.m8n8.x4.shared.b16 {%0,%1,%2,%3}, [%4];\n"
      : "=r"(d[0]),"=r"(d[1]),"=r"(d[2]),"=r"(d[3]) : "r"(saddr));
}
__device__ __forceinline__ void mma16(float* c, const uint32_t* a, uint32_t b0, uint32_t b1){
    asm volatile(
      "mma.sync.aligned.m16n8k16.row.col.f32.f16.f16.f32 "
      "{%0,%1,%2,%3},{%4,%5,%6,%7},{%8,%9},{%0,%1,%2,%3};\n"
      : "+f"(c[0]),"+f"(c[1]),"+f"(c[2]),"+f"(c[3])
      : "r"(a[0]),"r"(a[1]),"r"(a[2]),"r"(a[3]), "r"(b0),"r"(b1));
}

// 32x128x128 fp16 GEMM (f32 accum); 8 warps as 2(m) x 4(n); warp tile 16x32.
// A fp16 [m][k] swizzled; B fp16 [n][k] swizzled.
__device__ __forceinline__ void gemm32h(float (&acc)[4][4], uint32_t Ab, uint32_t Bb,
                                        int lane, int wm, int wn)
{
    uint32_t lrow = (lane&7) + ((lane>>3)&1)*8;
    uint32_t csel = (lane>>4)&1;
    uint32_t arow = wm*16 + lrow;
    uint32_t abase = Ab + (arow<<8);
    uint32_t axor  = arow & 7u;
    uint32_t brow = wn*32 + lrow;
    uint32_t bxor  = brow & 7u;
    uint32_t bb0 = Bb + (brow<<8);
    uint32_t bb1 = bb0 + (16u<<8);

    #pragma unroll
    for (int kk=0;kk<8;kk++){
        uint32_t a[4], b0[4], b1[4];
        uint32_t ac = ((uint32_t)(kk*2 + csel) ^ axor) << 4;
        uint32_t bc = ((uint32_t)(kk*2 + csel) ^ bxor) << 4;
        ldsm4(a,  abase + ac);
        ldsm4(b0, bb0 + bc);
        ldsm4(b1, bb1 + bc);
        mma16(acc[0], a, b0[0], b0[2]);
        mma16(acc[1], a, b0[1], b0[3]);
        mma16(acc[2], a, b1[0], b1[2]);
        mma16(acc[3], a, b1[1], b1[3]);
    }
}

#define ZERO_ACC(A) { _Pragma("unroll") for(int _n=0;_n<4;_n++) _Pragma("unroll") for(int _e=0;_e<4;_e++) (A)[_n][_e]=0.0f; }

// ---- prep: transpose + fp16-round + swizzle all 8 weight matrices ------
__global__ void prep_weights(const float* __restrict__ Wf, const float* __restrict__ Uf,
                             const float* __restrict__ Wu, const float* __restrict__ Uu,
                             const float* __restrict__ Wi, const float* __restrict__ Ui,
                             const float* __restrict__ Wo, const float* __restrict__ Uo)
{
    const float* srcs[8] = {Wf,Uf,Wu,Uu,Wi,Ui,Wo,Uo};
    const float* s = srcs[blockIdx.x];
    __half* d = wimg[blockIdx.x];
    for (int i = threadIdx.x; i < 128*128; i += blockDim.x){
        int n = i >> 7, k = i & 127;
        // swizzled image index: row n (128 halves), chunk = k>>3 ^ (n&7), inner = k&7
        int idx = n*128 + ((((k>>3) ^ (n&7)) & 15) << 3) + (k & 7);
        d[idx] = __float2half_rn(s[k*128 + n]);   // B[n][k] = W[k][n]
    }
}

__global__ void __launch_bounds__(THREADS, 2)
treelstm_kernel(const float* __restrict__ x,
                const float* __restrict__ child_h,
                const float* __restrict__ child_c,
                const float* __restrict__ bi, const float* __restrict__ bo,
                const float* __restrict__ bu, const float* __restrict__ bf,
                float* __restrict__ out, int N)
{
    extern __shared__ char smem[];
    uint32_t sb;
    asm("{ .reg .u64 t; cvta.to.shared.u64 t, %1; cvt.u32.u64 %0, t; }" : "=r"(sb) : "l"(smem));
    const uint32_t XHb  = sb + OFF_XH;
    const uint32_t HSHb = sb + OFF_HSH;
    const uint32_t BHb  = sb + OFF_BH;
    const uint32_t B0b  = sb + OFF_B0;
    const uint32_t B1b  = sb + OFF_B1;
    const uint32_t Wb   = sb + OFF_W;

    const int tid  = threadIdx.x;
    const int lane = tid & 31;
    const int g    = lane >> 2;
    const int r    = lane & 3;
    const int wid  = tid >> 5;
    const int wm   = wid & 1;           // 16-row half
    const int wn   = wid >> 1;          // 32-col group
    const int m0   = blockIdx.x * ROWS;

    const int Rr   = wm*16 + g;         // owned rows: Rr, Rr+8 (tile-local)
    const int Rg   = m0 + Rr;           // global rows

    float acc [4][4];
    float cacc[4][4];
    float xfv [4][4];   // xf during children, u during gates
    float hs  [4][4];

    #pragma unroll
    for (int nt=0;nt<4;nt++)
      #pragma unroll
      for (int e=0;e<4;e++){ cacc[nt][e]=0.f; hs[nt][e]=0.f; }

    // ---- prologue: x->B0 + Wf->W | ch0->B1 -----------------------------
    cpa_t32(B0b, x + (size_t)m0*128, 128, tid);
    cpa_w  (Wb, wimg[0], tid);
    CP_COMMIT();                                     // G1: x + Wf
    cpa_t32(B1b, child_h + ((size_t)m0*8 + 0)*128, 8*128, tid);
    CP_COMMIT();                                     // G2: ch0

    CP_WAIT(1); __syncthreads();                     // x + Wf visible
    // convert x slice -> XH (fp16)
    #pragma unroll
    for (int nt=0;nt<4;nt++){
        int C0 = wn*32 + nt*8 + 2*r;
        int ckf = C0>>2, inf = (C0&3)<<2;
        int ckh = C0>>3, inh = (C0&7)<<1;
        float2 v0 = *reinterpret_cast<const float2*>(smem + OFF_B0 + SWF(Rr,   ckf) + inf);
        float2 v1 = *reinterpret_cast<const float2*>(smem + OFF_B0 + SWF(Rr+8, ckf) + inf);
        *reinterpret_cast<__half2*>(smem + OFF_XH + SWH(Rr,   ckh) + inh) = __floats2half2_rn(v0.x, v0.y);
        *reinterpret_cast<__half2*>(smem + OFF_XH + SWH(Rr+8, ckh) + inh) = __floats2half2_rn(v1.x, v1.y);
    }
    __syncthreads();                                 // XH visible

    // ---- phase 1: xf = x @ Wf + bf --------------------------------------
    ZERO_ACC(acc);
    gemm32h(acc, XHb, Wb, lane, wm, wn);
    __syncthreads();                                 // W free
    cpa_w(Wb, wimg[1], tid); CP_COMMIT();            // G3: Uf
    cpa_t32(B0b, child_h + ((size_t)m0*8 + 1)*128, 8*128, tid);
    CP_COMMIT();                                     // G4: ch1

    #pragma unroll
    for (int nt=0;nt<4;nt++){
        int C0 = wn*32 + nt*8 + 2*r;
        float2 bv = *reinterpret_cast<const float2*>(bf + C0);
        xfv[nt][0] = acc[nt][0] + bv.x;
        xfv[nt][1] = acc[nt][1] + bv.y;
        xfv[nt][2] = acc[nt][2] + bv.x;
        xfv[nt][3] = acc[nt][3] + bv.y;
    }

    // ---- phase 2: children (staging ping-pong; Uf resident in W) --------
    for (int k=0;k<8;k++){
        uint32_t stg = (k&1) ? B0b : B1b;
        int stgOff   = (k&1) ? OFF_B0 : OFF_B1;
        if (k<7) { CP_WAIT(1); } else { CP_WAIT(0); }    // ch_k (+Uf at k=0) done
        __syncthreads();                                 // staging ready; BH free

        // hs += raw slice; convert to fp16 -> BH
        #pragma unroll
        for (int nt=0;nt<4;nt++){
            int C0 = wn*32 + nt*8 + 2*r;
            int ckf = C0>>2, inf = (C0&3)<<2;
            int ckh = C0>>3, inh = (C0&7)<<1;
            float2 v0 = *reinterpret_cast<const float2*>(smem + stgOff + SWF(Rr,   ckf) + inf);
            float2 v1 = *reinterpret_cast<const float2*>(smem + stgOff + SWF(Rr+8, ckf) + inf);
            hs[nt][0] += v0.x; hs[nt][1] += v0.y;
            hs[nt][2] += v1.x; hs[nt][3] += v1.y;
            *reinterpret_cast<__half2*>(smem + OFF_BH + SWH(Rr,   ckh) + inh) = __floats2half2_rn(v0.x, v0.y);
            *reinterpret_cast<__half2*>(smem + OFF_BH + SWH(Rr+8, ckh) + inh) = __floats2half2_rn(v1.x, v1.y);
        }
        // prefetch child_c[k]
        float2 cc0[4], cc1[4];
        #pragma unroll
        for (int nt=0;nt<4;nt++){
            int C0 = wn*32 + nt*8 + 2*r;
            cc0[nt] = __ldg(reinterpret_cast<const float2*>(child_c + ((size_t)Rg    *8 + k)*128 + C0));
            cc1[nt] = __ldg(reinterpret_cast<const float2*>(child_c + ((size_t)(Rg+8)*8 + k)*128 + C0));
        }
        __syncthreads();                                 // BH visible; staging free
        if (k+2 < 8){
            cpa_t32(stg, child_h + ((size_t)m0*8 + (k+2))*128, 8*128, tid);
            CP_COMMIT();
        }

        ZERO_ACC(acc);
        gemm32h(acc, BHb, Wb, lane, wm, wn);             // ch_k @ Uf

        #pragma unroll
        for (int nt=0;nt<4;nt++){
            cacc[nt][0] += sigf(xfv[nt][0] + acc[nt][0]) * cc0[nt].x;
            cacc[nt][1] += sigf(xfv[nt][1] + acc[nt][1]) * cc0[nt].y;
            cacc[nt][2] += sigf(xfv[nt][2] + acc[nt][2]) * cc1[nt].x;
            cacc[nt][3] += sigf(xfv[nt][3] + acc[nt][3]) * cc1[nt].y;
        }
    }

    // ---- gate prologue: hs -> HSH (fp16) ---------------------------------
    #pragma unroll
    for (int nt=0;nt<4;nt++){
        int C0 = wn*32 + nt*8 + 2*r;
        int ckh = C0>>3, inh = (C0&7)<<1;
        *reinterpret_cast<__half2*>(smem + OFF_HSH + SWH(Rr,   ckh) + inh) = __floats2half2_rn(hs[nt][0], hs[nt][1]);
        *reinterpret_cast<__half2*>(smem + OFF_HSH + SWH(Rr+8, ckh) + inh) = __floats2half2_rn(hs[nt][2], hs[nt][3]);
    }
    __syncthreads();                                   // last gemm done; W free; HSH visible
    cpa_w(Wb, wimg[2], tid); CP_COMMIT();              // Wu

    const float* bs[3] = {bu, bi, bo};

    // ---- phase 3: gates u, i, o ------------------------------------------
    for (int gate=0; gate<3; gate++){
        CP_WAIT(0); __syncthreads();                   // W_gate visible
        ZERO_ACC(acc);
        gemm32h(acc, XHb, Wb, lane, wm, wn);           // x @ W_g
        __syncthreads();                               // W free
        cpa_w(Wb, wimg[3 + 2*gate], tid); CP_COMMIT(); // U_g
        CP_WAIT(0); __syncthreads();
        gemm32h(acc, HSHb, Wb, lane, wm, wn);          // + hs @ U_g
        __syncthreads();                               // W free
        if (gate<2){ cpa_w(Wb, wimg[4 + 2*gate], tid); CP_COMMIT(); }

        const float* bp = bs[gate];
        #pragma unroll
        for (int nt=0;nt<4;nt++){
            int C0 = wn*32 + nt*8 + 2*r;
            float2 bv = *reinterpret_cast<const float2*>(bp + C0);
            float p0 = acc[nt][0] + bv.x;
            float p1 = acc[nt][1] + bv.y;
            float p2 = acc[nt][2] + bv.x;
            float p3 = acc[nt][3] + bv.y;
            if (gate == 0){
                xfv[nt][0] = tanhfast(p0);
                xfv[nt][1] = tanhfast(p1);
                xfv[nt][2] = tanhfast(p2);
                xfv[nt][3] = tanhfast(p3);
            } else if (gate == 1){
                cacc[nt][0] += sigf(p0) * xfv[nt][0];
                cacc[nt][1] += sigf(p1) * xfv[nt][1];
                cacc[nt][2] += sigf(p2) * xfv[nt][2];
                cacc[nt][3] += sigf(p3) * xfv[nt][3];
            } else {
                float c0 = cacc[nt][0], c1 = cacc[nt][1];
                float c2 = cacc[nt][2], c3 = cacc[nt][3];
                float h0 = sigf(p0) * tanhfast(c0);
                float h1 = sigf(p1) * tanhfast(c1);
                float h2 = sigf(p2) * tanhfast(c2);
                float h3 = sigf(p3) * tanhfast(c3);
                float* outh = out;
                float* outc = out + (size_t)N*128;
                *reinterpret_cast<float2*>(outh + (size_t) Rg   *128 + C0) = make_float2(h0,h1);
                *reinterpret_cast<float2*>(outh + (size_t)(Rg+8)*128 + C0) = make_float2(h2,h3);
                *reinterpret_cast<float2*>(outc + (size_t) Rg   *128 + C0) = make_float2(c0,c1);
                *reinterpret_cast<float2*>(outc + (size_t)(Rg+8)*128 + C0) = make_float2(c2,c3);
            }
        }
    }
}

extern "C" void kernel_launch(void* const* d_in, const int* in_sizes, int n_in,
                              void* d_out, int out_size)
{
    const float* x       = (const float*)d_in[0];
    const float* child_h = (const float*)d_in[1];
    const float* child_c = (const float*)d_in[2];
    const float* Wi = (const float*)d_in[3];
    const float* bi = (const float*)d_in[4];
    const float* Ui = (const float*)d_in[5];
    const float* Wo = (const float*)d_in[6];
    const float* bo = (const float*)d_in[7];
    const float* Uo = (const float*)d_in[8];
    const float* Wu = (const float*)d_in[9];
    const float* bu = (const float*)d_in[10];
    const float* Uu = (const float*)d_in[11];
    const float* Wf = (const float*)d_in[12];
    const float* bf = (const float*)d_in[13];
    const float* Uf = (const float*)d_in[14];
    float* out = (float*)d_out;

    int N = in_sizes[0] / 128;
    int blocks = N / ROWS;

    prep_weights<<<8, 256>>>(Wf, Uf, Wu, Uu, Wi, Ui, Wo, Uo);

    cudaFuncSetAttribute(treelstm_kernel,
                         cudaFuncAttributeMaxDynamicSharedMemorySize, SMEM_BYTES);
    treelstm_kernel<<<blocks, THREADS, SMEM_BYTES>>>(
        x, child_h, child_c, bi, bo, bu, bf, out, N);
}